// round 17
// baseline (speedup 1.0000x reference)
#include <cuda_runtime.h>
#include <cuda_fp16.h>
#include <math.h>
#include <stdint.h>

#define D 768
#define H 12
#define HD 64
#define DFF 3072
#define QKV3 2304
#define MAXTOK 8192
#define S_MAX 1024

// ---------------- scratch (static device globals; no allocation) ----------------
__device__ __half g_ln[MAXTOK * D];
__device__ __half g_qkv[MAXTOK * QKV3];
__device__ __half g_vT[H * HD * MAXTOK];
__device__ __half g_attn[MAXTOK * D];
__device__ float  g_x2[MAXTOK * D];
__device__ __half g_h[MAXTOK * D];
__device__ __half g_m[MAXTOK * DFF];
// transposed half weights: Wt[N][K]
#define WT_QKV 0
#define WT_O   1769472
#define WT_1   2359296
#define WT_2   4718592
__device__ __half g_wT[7077888];

// ---------------- helpers ----------------
__device__ __forceinline__ uint32_t pack2(float a, float b) {
    __half2 h = __floats2half2_rn(a, b);
    return *reinterpret_cast<uint32_t*>(&h);
}

__device__ __forceinline__ void mma_f16(
    float& c0, float& c1, float& c2, float& c3,
    uint32_t a0, uint32_t a1, uint32_t a2, uint32_t a3,
    uint32_t b0, uint32_t b1)
{
    asm volatile(
        "mma.sync.aligned.m16n8k16.row.col.f32.f16.f16.f32 "
        "{%0,%1,%2,%3}, {%4,%5,%6,%7}, {%8,%9}, {%0,%1,%2,%3};"
        : "+f"(c0), "+f"(c1), "+f"(c2), "+f"(c3)
        : "r"(a0), "r"(a1), "r"(a2), "r"(a3), "r"(b0), "r"(b1));
}

__device__ __forceinline__ void cpa16(uint32_t dst, const void* src) {
    asm volatile("cp.async.cg.shared.global [%0], [%1], 16;" :: "r"(dst), "l"(src));
}
#define CP_COMMIT asm volatile("cp.async.commit_group;")
#define CP_WAIT(n) asm volatile("cp.async.wait_group %0;" :: "n"(n))

// ---------------- weight prep: W[K,N] fp32 -> Wt[N,K] half ----------------
__global__ __launch_bounds__(256) void prep_w(
    const float* __restrict__ W, __half* __restrict__ Wt, int K, int N)
{
    __shared__ float t[32][33];
    int n0 = blockIdx.x * 32, k0 = blockIdx.y * 32;
    int tx = threadIdx.x & 31, ty = threadIdx.x >> 5;
    #pragma unroll
    for (int i = 0; i < 4; i++)
        t[ty + 8 * i][tx] = W[(size_t)(k0 + ty + 8 * i) * N + n0 + tx];
    __syncthreads();
    #pragma unroll
    for (int i = 0; i < 4; i++)
        Wt[(size_t)(n0 + ty + 8 * i) * K + k0 + tx] = __float2half_rn(t[tx][ty + 8 * i]);
}

// ---------------- V transpose: g_qkv V-part [token][c] -> g_vT[c][token] ----------------
__global__ __launch_bounds__(256) void prep_vT(
    const __half* __restrict__ qkv, __half* __restrict__ vT)
{
    __shared__ __half t[32][33];
    int c0 = blockIdx.x * 32, tok0 = blockIdx.y * 32;
    int tx = threadIdx.x & 31, ty = threadIdx.x >> 5;
    #pragma unroll
    for (int i = 0; i < 4; i++)
        t[ty + 8 * i][tx] = qkv[(size_t)(tok0 + ty + 8 * i) * QKV3 + 2 * D + c0 + tx];
    __syncthreads();
    #pragma unroll
    for (int i = 0; i < 4; i++)
        vT[(size_t)(c0 + ty + 8 * i) * MAXTOK + tok0 + tx] = t[tx][ty + 8 * i];
}

// ---------------- LayerNorm: one WARP per row, fp32 in -> half out ----------------
__global__ __launch_bounds__(256) void ln_kernel(
    const float* __restrict__ x, const float* __restrict__ g,
    const float* __restrict__ b, __half* __restrict__ out, int total)
{
    int row = blockIdx.x * 8 + (threadIdx.x >> 5);
    if (row >= total) return;
    int lane = threadIdx.x & 31;

    const float* xr = x + (size_t)row * D;
    float v[24];
    float s = 0.f, sq = 0.f;
    #pragma unroll
    for (int i = 0; i < 24; i++) {
        v[i] = xr[lane + i * 32];
        s += v[i];
        sq = fmaf(v[i], v[i], sq);
    }
    #pragma unroll
    for (int off = 16; off > 0; off >>= 1) {
        s  += __shfl_xor_sync(0xFFFFFFFFu, s, off);
        sq += __shfl_xor_sync(0xFFFFFFFFu, sq, off);
    }
    float mean = s * (1.0f / D);
    float var = sq * (1.0f / D) - mean * mean;
    float rstd = rsqrtf(var + 1e-6f);

    __half* orow = out + (size_t)row * D;
    #pragma unroll
    for (int i = 0; i < 24; i++) {
        int c = lane + i * 32;
        orow[c] = __float2half_rn((v[i] - mean) * rstd * g[c] + b[c]);
    }
}

// ---------------- fp16 tensor-core GEMM: KTILE=64, 3-stage cp.async, single sync/tile ----------------
// Block 128x128, warp 32x64. A smem [m][k], B smem [n][k], rows of 32 words (64 halves),
// stride 36 (=4 mod 32: conflict-free frag loads).
// EPI: 0 = bias -> half C ; 1 = bias + residual -> float C ; 2 = bias + GELU -> half C
#define GPAD 36
#define STAGES 3

template <int EPI>
__global__ __launch_bounds__(256, 2) void gemm_h(
    const __half* __restrict__ A, const __half* __restrict__ Bt,
    const float* __restrict__ bias, const float* __restrict__ res,
    void* __restrict__ Cv, int M, int N, int K)
{
    __shared__ uint32_t As[STAGES][128 * GPAD];
    __shared__ uint32_t Bs[STAGES][128 * GPAD];

    int tid  = threadIdx.x;
    int warp = tid >> 5, lane = tid & 31;
    int wm = (warp >> 1) * 32;
    int wn = (warp & 1) * 64;
    int g  = lane >> 2;
    int t4 = lane & 3;

    int bm = blockIdx.y * 128;
    int bn = blockIdx.x * 128;

    // staging: thread -> row tid/2, 64B half-row (tid&1); 4 cpa16 for A, 4 for B
    int row = tid >> 1;
    int hoff = (tid & 1);                 // 0/1 -> halves offset *32
    int gaRow = bm + row; if (gaRow >= M) gaRow = M - 1;
    const __half* Ag = A + (size_t)gaRow * K + hoff * 32;
    int gbRow = bn + row;
    const __half* Bg = Bt + (size_t)gbRow * K + hoff * 32;

    uint32_t aDst = (uint32_t)__cvta_generic_to_shared(&As[0][row * GPAD + hoff * 16]);
    uint32_t bDst = (uint32_t)__cvta_generic_to_shared(&Bs[0][row * GPAD + hoff * 16]);
    const uint32_t BUF = 128 * GPAD * 4;

    float acc[2][8][4];
    #pragma unroll
    for (int mi = 0; mi < 2; mi++)
        #pragma unroll
        for (int ni = 0; ni < 8; ni++)
            #pragma unroll
            for (int r = 0; r < 4; r++) acc[mi][ni][r] = 0.f;

    int T = K >> 6;      // 64-k tiles

    #pragma unroll
    for (int s = 0; s < STAGES - 1; s++) {
        if (s < T) {
            #pragma unroll
            for (int i = 0; i < 4; i++) {
                cpa16(aDst + s * BUF + i * 16, Ag + s * 64 + i * 8);
                cpa16(bDst + s * BUF + i * 16, Bg + s * 64 + i * 8);
            }
        }
        CP_COMMIT;
    }

    for (int t = 0; t < T; t++) {
        CP_WAIT(1);
        __syncthreads();

        int pf = t + STAGES - 1;
        if (pf < T) {
            uint32_t bo = (uint32_t)(pf % STAGES);
            #pragma unroll
            for (int i = 0; i < 4; i++) {
                cpa16(aDst + bo * BUF + i * 16, Ag + pf * 64 + i * 8);
                cpa16(bDst + bo * BUF + i * 16, Bg + pf * 64 + i * 8);
            }
        }
        CP_COMMIT;

        const uint32_t* Asb = As[t % STAGES];
        const uint32_t* Bsb = Bs[t % STAGES];

        #pragma unroll
        for (int ks = 0; ks < 4; ks++) {
            uint32_t af[2][4];
            #pragma unroll
            for (int mi = 0; mi < 2; mi++) {
                int r0 = wm + mi * 16 + g;
                af[mi][0] = Asb[r0 * GPAD + ks * 8 + t4];
                af[mi][1] = Asb[(r0 + 8) * GPAD + ks * 8 + t4];
                af[mi][2] = Asb[r0 * GPAD + ks * 8 + 4 + t4];
                af[mi][3] = Asb[(r0 + 8) * GPAD + ks * 8 + 4 + t4];
            }
            uint32_t bf[8][2];
            #pragma unroll
            for (int ni = 0; ni < 8; ni++) {
                int c0 = wn + ni * 8 + g;
                bf[ni][0] = Bsb[c0 * GPAD + ks * 8 + t4];
                bf[ni][1] = Bsb[c0 * GPAD + ks * 8 + 4 + t4];
            }
            #pragma unroll
            for (int mi = 0; mi < 2; mi++)
                #pragma unroll
                for (int ni = 0; ni < 8; ni++)
                    mma_f16(acc[mi][ni][0], acc[mi][ni][1], acc[mi][ni][2], acc[mi][ni][3],
                            af[mi][0], af[mi][1], af[mi][2], af[mi][3],
                            bf[ni][0], bf[ni][1]);
        }
    }

    // ---- epilogue ----
    #pragma unroll
    for (int mi = 0; mi < 2; mi++) {
        #pragma unroll
        for (int half = 0; half < 2; half++) {
            int orow = bm + wm + mi * 16 + half * 8 + g;
            if (orow >= M) continue;
            #pragma unroll
            for (int ni = 0; ni < 8; ni++) {
                int col = bn + wn + ni * 8 + t4 * 2;
                float v0 = acc[mi][ni][half * 2 + 0] + bias[col];
                float v1 = acc[mi][ni][half * 2 + 1] + bias[col + 1];
                if (EPI == 1) {
                    v0 += res[(size_t)orow * N + col];
                    v1 += res[(size_t)orow * N + col + 1];
                }
                if (EPI == 2) {
                    v0 = 0.5f * v0 * (1.0f + erff(v0 * 0.70710678118654752f));
                    v1 = 0.5f * v1 * (1.0f + erff(v1 * 0.70710678118654752f));
                }
                if (EPI == 1) {
                    float2 o; o.x = v0; o.y = v1;
                    *(float2*)((float*)Cv + (size_t)orow * N + col) = o;
                } else {
                    *(uint32_t*)((__half*)Cv + (size_t)orow * N + col) = pack2(v0, v1);
                }
            }
        }
    }
}

// ---------------- fp16 flash attention: Q-tile 128, 3-stage K/V, P in registers (R15) ----------------
#define KT 32
#define QSW 36
#define VSW 20
#define QT2 128
#define KSTG 3

__global__ __launch_bounds__(256) void attn_h(
    const __half* __restrict__ qkv, const __half* __restrict__ vT,
    const int* __restrict__ cu, __half* __restrict__ out)
{
    __shared__ uint32_t Qs[QT2 * QSW];
    __shared__ uint32_t Ks[KSTG][KT * QSW];
    __shared__ uint32_t Vs[KSTG][HD * VSW];

    int b = blockIdx.z, h = blockIdx.y, qt = blockIdx.x;
    int s0 = cu[b];
    int len = cu[b + 1] - s0;
    if (qt * QT2 >= len) return;

    int tid = threadIdx.x;
    int warp = tid >> 5, lane = tid & 31;
    int g = lane >> 2, t4 = lane & 3;

    int krow = tid >> 3;
    int kchk = tid & 7;
    uint32_t kDst = (uint32_t)__cvta_generic_to_shared(&Ks[0][krow * QSW + kchk * 4]);
    int vrow = tid >> 2;
    int vchk = tid & 3;
    uint32_t vDst = (uint32_t)__cvta_generic_to_shared(&Vs[0][vrow * VSW + vchk * 4]);
    const __half* vbase = vT + (size_t)(h * HD + vrow) * MAXTOK + s0;
    const uint32_t KBUF = KT * QSW * 4;
    const uint32_t VBUF = HD * VSW * 4;
    int ntile = (len + KT - 1) / KT;

    #pragma unroll
    for (int s = 0; s < KSTG - 1; s++) {
        if (s < ntile) {
            int gk = s * KT + krow; if (gk >= len) gk = len - 1;
            cpa16(kDst + (uint32_t)(s * KBUF),
                  qkv + (size_t)(s0 + gk) * QKV3 + D + h * HD + kchk * 8);
            int tk = s * KT + vchk * 8; if (tk >= len) tk = 0;
            cpa16(vDst + (uint32_t)(s * VBUF), vbase + tk);
        }
        CP_COMMIT;
    }

    {
        int qr = tid >> 1;
        int qh = (tid & 1);
        int gq = qt * QT2 + qr; if (gq >= len) gq = len - 1;
        const uint32_t* src = (const uint32_t*)(qkv + (size_t)(s0 + gq) * QKV3 + h * HD + qh * 32);
        uint32_t* dst = &Qs[qr * QSW + qh * 16];
        const __half2 sc = __float2half2_rn(0.125f);
        #pragma unroll
        for (int i = 0; i < 16; i++) {
            __half2 v = *(const __half2*)&src[i];
            v = __hmul2(v, sc);
            dst[i] = *(uint32_t*)&v;
        }
    }
    __syncthreads();

    uint32_t qf[4][4];
    int wq = warp * 16;
    #pragma unroll
    for (int ks = 0; ks < 4; ks++) {
        qf[ks][0] = Qs[(wq + g) * QSW + ks * 8 + t4];
        qf[ks][1] = Qs[(wq + g + 8) * QSW + ks * 8 + t4];
        qf[ks][2] = Qs[(wq + g) * QSW + ks * 8 + 4 + t4];
        qf[ks][3] = Qs[(wq + g + 8) * QSW + ks * 8 + 4 + t4];
    }

    float oa[8][4];
    #pragma unroll
    for (int vn = 0; vn < 8; vn++)
        #pragma unroll
        for (int r = 0; r < 4; r++) oa[vn][r] = 0.f;
    float lp0 = 0.f, lp1 = 0.f;

    for (int kt = 0; kt < ntile; kt++) {
        CP_WAIT(1);
        __syncthreads();

        int pf = kt + KSTG - 1;
        if (pf < ntile) {
            uint32_t bo = (uint32_t)(pf % KSTG);
            int gk = pf * KT + krow; if (gk >= len) gk = len - 1;
            cpa16(kDst + bo * KBUF,
                  qkv + (size_t)(s0 + gk) * QKV3 + D + h * HD + kchk * 8);
            int tk = pf * KT + vchk * 8; if (tk >= len) tk = 0;
            cpa16(vDst + bo * VBUF, vbase + tk);
        }
        CP_COMMIT;

        const uint32_t* Kb = Ks[kt % KSTG];
        const uint32_t* Vb = Vs[kt % KSTG];

        float sa[4][4];
        #pragma unroll
        for (int kn = 0; kn < 4; kn++)
            #pragma unroll
            for (int r = 0; r < 4; r++) sa[kn][r] = 0.f;

        #pragma unroll
        for (int ks = 0; ks < 4; ks++) {
            #pragma unroll
            for (int kn = 0; kn < 4; kn++) {
                uint32_t b0 = Kb[(kn * 8 + g) * QSW + ks * 8 + t4];
                uint32_t b1 = Kb[(kn * 8 + g) * QSW + ks * 8 + 4 + t4];
                mma_f16(sa[kn][0], sa[kn][1], sa[kn][2], sa[kn][3],
                        qf[ks][0], qf[ks][1], qf[ks][2], qf[ks][3], b0, b1);
            }
        }

        uint32_t ph[4][2];
        #pragma unroll
        for (int kn = 0; kn < 4; kn++) {
            int c0 = kt * KT + kn * 8 + 2 * t4;
            float p0 = (c0     < len) ? __expf(sa[kn][0]) : 0.f;
            float p1 = (c0 + 1 < len) ? __expf(sa[kn][1]) : 0.f;
            float p2 = (c0     < len) ? __expf(sa[kn][2]) : 0.f;
            float p3 = (c0 + 1 < len) ? __expf(sa[kn][3]) : 0.f;
            lp0 += p0 + p1;
            lp1 += p2 + p3;
            ph[kn][0] = pack2(p0, p1);
            ph[kn][1] = pack2(p2, p3);
        }

        #pragma unroll
        for (int ks = 0; ks < 2; ks++) {
            uint32_t a0 = ph[2 * ks][0];
            uint32_t a1 = ph[2 * ks][1];
            uint32_t a2 = ph[2 * ks + 1][0];
            uint32_t a3 = ph[2 * ks + 1][1];
            #pragma unroll
            for (int vn = 0; vn < 8; vn++) {
                uint32_t b0 = Vb[(vn * 8 + g) * VSW + ks * 8 + t4];
                uint32_t b1 = Vb[(vn * 8 + g) * VSW + ks * 8 + 4 + t4];
                mma_f16(oa[vn][0], oa[vn][1], oa[vn][2], oa[vn][3],
                        a0, a1, a2, a3, b0, b1);
            }
        }
    }

    lp0 += __shfl_xor_sync(0xFFFFFFFFu, lp0, 1);
    lp0 += __shfl_xor_sync(0xFFFFFFFFu, lp0, 2);
    lp1 += __shfl_xor_sync(0xFFFFFFFFu, lp1, 1);
    lp1 += __shfl_xor_sync(0xFFFFFFFFu, lp1, 2);
    float inv0 = 1.f / lp0, inv1 = 1.f / lp1;

    int q0 = qt * QT2 + wq + g;
    int q1 = q0 + 8;
    if (q0 < len) {
        __half* op = out + (size_t)(s0 + q0) * D + h * HD;
        #pragma unroll
        for (int vn = 0; vn < 8; vn++)
            *(uint32_t*)(op + vn * 8 + 2 * t4) = pack2(oa[vn][0] * inv0, oa[vn][1] * inv0);
    }
    if (q1 < len) {
        __half* op = out + (size_t)(s0 + q1) * D + h * HD;
        #pragma unroll
        for (int vn = 0; vn < 8; vn++)
            *(uint32_t*)(op + vn * 8 + 2 * t4) = pack2(oa[vn][2] * inv1, oa[vn][3] * inv1);
    }
}

// ---------------- launch ----------------
extern "C" void kernel_launch(void* const* d_in, const int* in_sizes, int n_in,
                              void* d_out, int out_size)
{
    const float* x     = (const float*)d_in[0];
    const int*   cu    = (const int*)  d_in[1];
    const float* g1    = (const float*)d_in[2];
    const float* beta1 = (const float*)d_in[3];
    const float* Wqkv  = (const float*)d_in[4];
    const float* bqkv  = (const float*)d_in[5];
    const float* Wo    = (const float*)d_in[6];
    const float* bo    = (const float*)d_in[7];
    const float* g2    = (const float*)d_in[8];
    const float* beta2 = (const float*)d_in[9];
    const float* W1    = (const float*)d_in[10];
    const float* bfc1  = (const float*)d_in[11];
    const float* W2    = (const float*)d_in[12];
    const float* bfc2  = (const float*)d_in[13];
    float* out = (float*)d_out;

    int total = in_sizes[0] / D;
    int B = in_sizes[1] - 1;

    __half *p_ln, *p_qkv, *p_vT, *p_attn, *p_h, *p_m, *p_wT;
    float *p_x2;
    cudaGetSymbolAddress((void**)&p_ln,   g_ln);
    cudaGetSymbolAddress((void**)&p_qkv,  g_qkv);
    cudaGetSymbolAddress((void**)&p_vT,   g_vT);
    cudaGetSymbolAddress((void**)&p_attn, g_attn);
    cudaGetSymbolAddress((void**)&p_x2,   g_x2);
    cudaGetSymbolAddress((void**)&p_h,    g_h);
    cudaGetSymbolAddress((void**)&p_m,    g_m);
    cudaGetSymbolAddress((void**)&p_wT,   g_wT);

    int mtiles = (total + 127) / 128;
    int lnblocks = (total + 7) / 8;

    prep_w<<<dim3(QKV3 / 32, D / 32), 256>>>(Wqkv, p_wT + WT_QKV, D, QKV3);
    prep_w<<<dim3(D / 32, D / 32), 256>>>(Wo, p_wT + WT_O, D, D);
    prep_w<<<dim3(DFF / 32, D / 32), 256>>>(W1, p_wT + WT_1, D, DFF);
    prep_w<<<dim3(D / 32, DFF / 32), 256>>>(W2, p_wT + WT_2, DFF, D);

    ln_kernel<<<lnblocks, 256>>>(x, g1, beta1, p_ln, total);
    gemm_h<0><<<dim3(QKV3 / 128, mtiles), 256>>>(p_ln, p_wT + WT_QKV, bqkv, nullptr, p_qkv, total, QKV3, D);
    prep_vT<<<dim3(D / 32, (total + 31) / 32), 256>>>(p_qkv, p_vT);
    attn_h<<<dim3(S_MAX / QT2, H, B), 256>>>(p_qkv, p_vT, cu, p_attn);
    gemm_h<1><<<dim3(D / 128, mtiles), 256>>>(p_attn, p_wT + WT_O, bo, x, p_x2, total, D, D);
    ln_kernel<<<lnblocks, 256>>>(p_x2, g2, beta2, p_h, total);
    gemm_h<2><<<dim3(DFF / 128, mtiles), 256>>>(p_h, p_wT + WT_1, bfc1, nullptr, p_m, total, DFF, D);
    gemm_h<1><<<dim3(D / 128, mtiles), 256>>>(p_m, p_wT + WT_2, bfc2, p_x2, out, total, D, DFF);
}